// round 17
// baseline (speedup 1.0000x reference)
#include <cuda_runtime.h>
#include <math.h>
#include <stdint.h>

// BatchHardTripletLoss on GB300 — mma.sync tf32 path, warp-pair-local B staging
// via cp.async double buffers (no block-wide syncs in mainloop), fused finish.
//
// inputs: d_in[0] = embeddings float32 [8192,128]
//         d_in[1] = labels (int32 in practice; runtime layout probe kept)
// output: d_out[0] = scalar float32 loss

#define BB 8192
#define DD 128
#define BM 128
#define BN 128
#define NCOLGROUPS 8
#define CT_PER_GROUP 8
#define LDA 132                         // smem row stride (floats), conflict-free

// smem layout (floats)
#define OF_A    0
#define QSZ     (32 * LDA)              // 4224 floats per B quarter buffer
#define OF_B    (128 * LDA)             // 16896
#define OF_SQC  (OF_B + 8 * QSZ)        // 16896 + 33792 = 50688
#define OF_LABC (OF_SQC + 1024)
#define SM_FLOATS (OF_LABC + 1024)      // 52736 floats = 210944 bytes

// ---------------------------------------------------------------------------
// Device scratch
// ---------------------------------------------------------------------------
__device__ float        g_embr[BB * DD];   // tf32-rounded embeddings (4 MB)
__device__ float        g_sq [BB];
__device__ int          g_lab[BB];
__device__ unsigned int g_hp2[BB];   // float bits of max same-class d^2
__device__ unsigned int g_hn2[BB];   // float bits of min diff-class d^2 (+inf init)
__device__ unsigned int g_done;
__device__ int          g_is64;

static __device__ __forceinline__ float to_tf32(float x) {
    float r;
    asm("cvt.rna.tf32.f32 %0, %1;" : "=f"(r) : "f"(x));
    return r;
}
static __device__ __forceinline__ uint32_t smem_u32(const void* p) {
    uint32_t a;
    asm("{ .reg .u64 t; cvta.to.shared.u64 t, %1; cvt.u32.u64 %0, t; }"
        : "=r"(a) : "l"(p));
    return a;
}
static __device__ __forceinline__ void cp16(uint32_t s, const void* g) {
    asm volatile("cp.async.cg.shared.global [%0], [%1], 16;" :: "r"(s), "l"(g));
}

#define MMA_TF32(c, a, b) \
    asm volatile( \
        "mma.sync.aligned.m16n8k8.row.col.f32.tf32.tf32.f32 " \
        "{%0,%1,%2,%3}, {%4,%5,%6,%7}, {%8,%9}, {%0,%1,%2,%3};" \
        : "+f"((c)[0]), "+f"((c)[1]), "+f"((c)[2]), "+f"((c)[3]) \
        : "r"((a)[0]), "r"((a)[1]), "r"((a)[2]), "r"((a)[3]), \
          "r"((b)[0]), "r"((b)[1]))

// ---------------------------------------------------------------------------
// Kernel 0: probe label dtype (int32 vs int64-LE); reset completion counter.
// ---------------------------------------------------------------------------
__global__ void probe_kernel(const int* __restrict__ lab32) {
    __shared__ int bad;
    if (threadIdx.x == 0) { bad = 0; g_done = 0u; }
    __syncthreads();
    int any = 0;
    for (int i = 1 + 2 * threadIdx.x; i < BB; i += 2 * blockDim.x)
        any |= (lab32[i] != 0);
    if (any) atomicOr(&bad, 1);
    __syncthreads();
    if (threadIdx.x == 0) g_is64 = bad ? 0 : 1;
}

// ---------------------------------------------------------------------------
// Kernel 1: exact fp32 row norms, tf32-rounded embedding copy, labels, init.
// ---------------------------------------------------------------------------
__global__ void prep_kernel(const float* __restrict__ emb,
                            const int* __restrict__ lab32) {
    int row  = blockIdx.x * 8 + (threadIdx.x >> 5);
    int lane = threadIdx.x & 31;
    float4 v = reinterpret_cast<const float4*>(emb)[row * (DD / 4) + lane];
    float s = v.x * v.x + v.y * v.y + v.z * v.z + v.w * v.w;
    float4 w;
    w.x = to_tf32(v.x); w.y = to_tf32(v.y); w.z = to_tf32(v.z); w.w = to_tf32(v.w);
    reinterpret_cast<float4*>(g_embr)[row * (DD / 4) + lane] = w;
    #pragma unroll
    for (int o = 16; o; o >>= 1) s += __shfl_xor_sync(0xffffffffu, s, o);
    if (lane == 0) {
        g_sq[row]  = s;
        g_lab[row] = g_is64 ? lab32[2 * row] : lab32[row];
        g_hp2[row] = 0u;
        g_hn2[row] = 0x7f800000u;
    }
}

// ---------------------------------------------------------------------------
// Kernel 2: mma.sync tf32 E@E^T fused with masked row max/min of d^2.
// grid = (64 row tiles, 8 col groups) x 256 threads; warps 2(M) x 4(N).
// Each warp-pair (wn) owns its 32-col B quarter: cp.async double-buffered,
// synchronized only by named pair barriers. Last block computes the loss.
// ---------------------------------------------------------------------------
__global__ __launch_bounds__(256, 1)
void dist_kernel(float* __restrict__ out) {
    extern __shared__ float sm[];
    __shared__ unsigned s_ticket;
    const uint32_t sb = smem_u32(sm);
    float* As   = sm + OF_A;
    float* sqc  = sm + OF_SQC;
    int*   labc = reinterpret_cast<int*>(sm + OF_LABC);
    const unsigned* Au = reinterpret_cast<const unsigned*>(As);

    const int tid  = threadIdx.x;
    const int wid  = tid >> 5;
    const int lane = tid & 31;
    const int g    = lane >> 2;
    const int t    = lane & 3;
    const int wm   = wid & 1;
    const int wn   = wid >> 1;
    const int ptid = tid & 63;           // thread id within warp-pair
    const int barid = 1 + wn;
    const int rowBase  = blockIdx.x * BM;
    const int colBase0 = blockIdx.y * CT_PER_GROUP * BN;

    // ---- stage A tile + col sq/labels window ----
    #pragma unroll
    for (int it = 0; it < 16; it++) {
        int e = tid + 256 * it, row = e >> 5, k4 = e & 31;
        float4 v = reinterpret_cast<const float4*>(g_embr + (rowBase + row) * DD)[k4];
        *reinterpret_cast<float4*>(As + row * LDA + k4 * 4) = v;
    }
    #pragma unroll
    for (int r = 0; r < 4; r++) {
        int idx = tid + 256 * r;
        sqc[idx]  = g_sq[colBase0 + idx];
        labc[idx] = g_lab[colBase0 + idx];
    }

    // ---- prologue: cp.async quarter for tile 0 into buf 0 ----
    {
        const float* src = g_embr + (colBase0 + wn * 32) * DD;
        uint32_t qb = sb + (uint32_t)(OF_B + (wn * 2 + 0) * QSZ) * 4u;
        #pragma unroll
        for (int it = 0; it < 16; it++) {
            int e = ptid + 64 * it, lrow = e >> 5, k4 = e & 31;
            cp16(qb + (uint32_t)(lrow * LDA + k4 * 4) * 4u, src + lrow * DD + k4 * 4);
        }
        asm volatile("cp.async.commit_group;");
    }

    // per-thread row constants
    float sqr8[4][2]; int labr8[4][2];
    #pragma unroll
    for (int i = 0; i < 4; i++)
        #pragma unroll
        for (int h = 0; h < 2; h++) {
            int r = rowBase + wm * 64 + i * 16 + g + 8 * h;
            sqr8[i][h]  = g_sq[r];
            labr8[i][h] = g_lab[r];
        }
    float hp2[4][2], hn2[4][2];
    #pragma unroll
    for (int i = 0; i < 4; i++)
        #pragma unroll
        for (int h = 0; h < 2; h++) { hp2[i][h] = 0.0f; hn2[i][h] = INFINITY; }

    __syncthreads();   // As + sqc/labc visible to all

    for (int ct = 0; ct < CT_PER_GROUP; ct++) {
        const int buf = ct & 1;

        // issue next quarter into the other buffer (WAR-safe: pair barrier at
        // end of previous iteration ordered it after both warps' mma reads)
        if (ct + 1 < CT_PER_GROUP) {
            const float* src = g_embr + (colBase0 + (ct + 1) * BN + wn * 32) * DD;
            uint32_t qb = sb + (uint32_t)(OF_B + (wn * 2 + (buf ^ 1)) * QSZ) * 4u;
            #pragma unroll
            for (int it = 0; it < 16; it++) {
                int e = ptid + 64 * it, lrow = e >> 5, k4 = e & 31;
                cp16(qb + (uint32_t)(lrow * LDA + k4 * 4) * 4u, src + lrow * DD + k4 * 4);
            }
        }
        asm volatile("cp.async.commit_group;");    // (empty group on last iter)
        asm volatile("cp.async.wait_group 1;");    // current tile's data landed
        asm volatile("bar.sync %0, 64;" :: "r"(barid));   // partner's too

        const unsigned* Bu =
            reinterpret_cast<const unsigned*>(sm + OF_B + (wn * 2 + buf) * QSZ);

        float acc[4][4][4];
        #pragma unroll
        for (int i = 0; i < 4; i++)
            #pragma unroll
            for (int j = 0; j < 4; j++)
                #pragma unroll
                for (int q = 0; q < 4; q++) acc[i][j][q] = 0.0f;

        // fragment-double-buffered k loop (16 x k8)
        unsigned Af[2][16], Bf[2][8];
        {
            const int c0 = t;
            #pragma unroll
            for (int i = 0; i < 4; i++) {
                int r = wm * 64 + i * 16 + g;
                Af[0][i * 4 + 0] = Au[r * LDA + c0];
                Af[0][i * 4 + 1] = Au[(r + 8) * LDA + c0];
                Af[0][i * 4 + 2] = Au[r * LDA + c0 + 4];
                Af[0][i * 4 + 3] = Au[(r + 8) * LDA + c0 + 4];
            }
            #pragma unroll
            for (int j = 0; j < 4; j++) {
                int rb = j * 8 + g;
                Bf[0][j * 2]     = Bu[rb * LDA + c0];
                Bf[0][j * 2 + 1] = Bu[rb * LDA + c0 + 4];
            }
        }
        #pragma unroll
        for (int s = 0; s < 16; s++) {
            const int cur = s & 1;
            if (s < 15) {
                const int nxt = cur ^ 1, c0 = (s + 1) * 8 + t;
                #pragma unroll
                for (int i = 0; i < 4; i++) {
                    int r = wm * 64 + i * 16 + g;
                    Af[nxt][i * 4 + 0] = Au[r * LDA + c0];
                    Af[nxt][i * 4 + 1] = Au[(r + 8) * LDA + c0];
                    Af[nxt][i * 4 + 2] = Au[r * LDA + c0 + 4];
                    Af[nxt][i * 4 + 3] = Au[(r + 8) * LDA + c0 + 4];
                }
                #pragma unroll
                for (int j = 0; j < 4; j++) {
                    int rb = j * 8 + g;
                    Bf[nxt][j * 2]     = Bu[rb * LDA + c0];
                    Bf[nxt][j * 2 + 1] = Bu[rb * LDA + c0 + 4];
                }
            }
            #pragma unroll
            for (int i = 0; i < 4; i++)
                #pragma unroll
                for (int j = 0; j < 4; j++)
                    MMA_TF32(acc[i][j], &Af[cur][i * 4], &Bf[cur][j * 2]);
        }

        // fused epilogue straight from accumulators
        const float* sq_c = sqc + ct * BN + wn * 32;
        const int*   lb_c = labc + ct * BN + wn * 32;
        #pragma unroll
        for (int j = 0; j < 4; j++) {
            int cb = j * 8 + 2 * t;
            float s0 = sq_c[cb], s1 = sq_c[cb + 1];
            int   l0 = lb_c[cb], l1 = lb_c[cb + 1];
            #pragma unroll
            for (int i = 0; i < 4; i++) {
                #pragma unroll
                for (int h = 0; h < 2; h++) {
                    float d2a = fmaxf(sqr8[i][h] + s0 - 2.0f * acc[i][j][2 * h],     0.0f);
                    float d2b = fmaxf(sqr8[i][h] + s1 - 2.0f * acc[i][j][2 * h + 1], 0.0f);
                    bool sa = (labr8[i][h] == l0);
                    bool sb = (labr8[i][h] == l1);
                    hp2[i][h] = fmaxf(hp2[i][h], sa ? d2a : 0.0f);
                    hn2[i][h] = fminf(hn2[i][h], sa ? INFINITY : d2a);
                    hp2[i][h] = fmaxf(hp2[i][h], sb ? d2b : 0.0f);
                    hn2[i][h] = fminf(hn2[i][h], sb ? INFINITY : d2b);
                }
            }
        }

        asm volatile("bar.sync %0, 64;" :: "r"(barid));   // pair done reading buf
    }

    // ---- reduction: quad-shuffle over t, smem over wn, one atomic per row ----
    __syncthreads();           // everyone done with As; reuse as scratch
    float* redp = As;          // 128 x 4
    float* redn = As + 512;
    #pragma unroll
    for (int i = 0; i < 4; i++)
        #pragma unroll
        for (int h = 0; h < 2; h++) {
            float mp = hp2[i][h], mn = hn2[i][h];
            mp = fmaxf(mp, __shfl_xor_sync(0xffffffffu, mp, 1));
            mp = fmaxf(mp, __shfl_xor_sync(0xffffffffu, mp, 2));
            mn = fminf(mn, __shfl_xor_sync(0xffffffffu, mn, 1));
            mn = fminf(mn, __shfl_xor_sync(0xffffffffu, mn, 2));
            if (t == 0) {
                int r = wm * 64 + i * 16 + g + 8 * h;
                redp[r * 4 + wn] = mp;
                redn[r * 4 + wn] = mn;
            }
        }
    __syncthreads();
    if (tid < BM) {
        float mx = redp[tid * 4], mn = redn[tid * 4];
        #pragma unroll
        for (int w = 1; w < 4; w++) {
            mx = fmaxf(mx, redp[tid * 4 + w]);
            mn = fminf(mn, redn[tid * 4 + w]);
        }
        atomicMax(&g_hp2[rowBase + tid], __float_as_uint(mx));
        atomicMin(&g_hn2[rowBase + tid], __float_as_uint(mn));
    }

    // ---- fused finish: last block to arrive computes the scalar loss ----
    __threadfence();
    __syncthreads();
    if (tid == 0) s_ticket = atomicAdd(&g_done, 1u);
    __syncthreads();
    if (s_ticket == (unsigned)(gridDim.x * gridDim.y - 1)) {
        __threadfence();
        float s = 0.0f;
        for (int i = tid; i < BB; i += 256) {
            float hp = sqrtf(__uint_as_float(g_hp2[i]));
            float hn = sqrtf(__uint_as_float(g_hn2[i]));   // +inf -> relu 0
            s += fmaxf(hp - hn + 1.0f, 0.0f);
        }
        #pragma unroll
        for (int o = 16; o; o >>= 1) s += __shfl_xor_sync(0xffffffffu, s, o);
        if (lane == 0) sm[wid] = s;
        __syncthreads();
        if (tid == 0) {
            float v = 0.0f;
            #pragma unroll
            for (int w = 0; w < 8; w++) v += sm[w];
            out[0] = v / (float)BB;
        }
    }
}

// ---------------------------------------------------------------------------
extern "C" void kernel_launch(void* const* d_in, const int* in_sizes, int n_in,
                              void* d_out, int out_size) {
    const float* emb   = (const float*)d_in[0];
    const int*   lab32 = (const int*)d_in[1];
    float*       out   = (float*)d_out;
    (void)in_sizes; (void)n_in; (void)out_size;

    cudaFuncSetAttribute(dist_kernel, cudaFuncAttributeMaxDynamicSharedMemorySize,
                         SM_FLOATS * 4);

    probe_kernel<<<1, 256>>>(lab32);
    prep_kernel<<<BB / 8, 256>>>(emb, lab32);
    dim3 grid(BB / BM, NCOLGROUPS);
    dist_kernel<<<grid, 256, SM_FLOATS * 4>>>(out);
}